// round 2
// baseline (speedup 1.0000x reference)
#include <cuda_runtime.h>
#include <cuda_bf16.h>

#define L_FFT   1024
#define NBINS   513
#define NBATCH  16
#define NCH     8
#define NT      250
#define NPAIRS  28
#define NLAGS   64
#define EPS_PHAT 1e-8f

// Scratch: spectra of all (b, m, t) rows. 16*8*250*513 complex = ~131 MB.
__device__ float2 g_X[(size_t)NBATCH * NCH * NT * NBINS];

__constant__ int c_i1[NPAIRS] = {0,0,0,0,0,0,0,1,1,1,1,1,1,2,2,2,2,2,3,3,3,3,4,4,4,5,5,6};
__constant__ int c_i2[NPAIRS] = {1,2,3,4,5,6,7,2,3,4,5,6,7,3,4,5,6,7,4,5,6,7,5,6,7,6,7,7};

__device__ __forceinline__ float2 cadd(float2 a, float2 b){ return make_float2(a.x+b.x, a.y+b.y); }
__device__ __forceinline__ float2 csub(float2 a, float2 b){ return make_float2(a.x-b.x, a.y-b.y); }
__device__ __forceinline__ float2 cmul(float2 a, float2 b){ return make_float2(a.x*b.x - a.y*b.y, a.x*b.y + a.y*b.x); }

// 512-point Stockham DIF FFT in shared memory, 128 threads per block.
// SIGN = -1: forward (e^{-2pi i k n / 512}); SIGN = +1: inverse kernel (unnormalized).
// T[j] = e^{+2 pi i j / 1024}  (so stage twiddle e^{+-2pi i p/n} = T[p << (10-log2 n)] (conj for fwd)).
// Input in a (natural order); returns pointer to result buffer (natural order).
template <int SIGN>
__device__ __forceinline__ float2* fft512(float2* a, float2* b, const float2* T, int tid) {
    float2* cur = a;
    float2* nxt = b;
    int n = 512, ls = 0, shift = 1;  // ls = log2(s), tw index = p << shift
    #pragma unroll
    for (int st = 0; st < 9; st++) {
        int m = n >> 1;
        #pragma unroll
        for (int ff = 0; ff < 2; ff++) {
            int f = tid + ff * 128;              // f in [0, 256): m*s = 256 butterflies
            int p = f >> ls;
            int q = f & ((1 << ls) - 1);
            float2 w = T[p << shift];
            if (SIGN < 0) w.y = -w.y;
            float2 c0 = cur[q + (p << ls)];
            float2 c1 = cur[q + ((p + m) << ls)];
            nxt[q + ((2 * p) << ls)]     = cadd(c0, c1);
            nxt[q + ((2 * p + 1) << ls)] = cmul(csub(c0, c1), w);
        }
        __syncthreads();
        float2* tmp = cur; cur = nxt; nxt = tmp;
        n = m; ls += 1; shift += 1;
    }
    return cur;
}

// ---------------- Kernel A: forward rfft of each (b, m, t) row ----------------
// One block per row. Real 1024-pt rfft via complex 512-pt FFT of packed even/odd.
__global__ __launch_bounds__(128) void fwd_fft_kernel(const float* __restrict__ x) {
    __shared__ float2 T[512];
    __shared__ float2 bufA[512];
    __shared__ float2 bufB[512];
    int tid = threadIdx.x;
    int row = blockIdx.x;  // (b*8 + m)*250 + t
    const float2* xin = reinterpret_cast<const float2*>(x + (size_t)row * L_FFT);

    #pragma unroll
    for (int j = tid; j < 512; j += 128) {
        float sv, cv;
        sincospif(j * (1.0f / 512.0f), &sv, &cv);  // angle = 2*pi*j/1024
        T[j] = make_float2(cv, sv);
        bufA[j] = xin[j];  // z[n] = x[2n] + i x[2n+1]
    }
    __syncthreads();

    float2* Z = fft512<-1>(bufA, bufB, T, tid);

    // Unpack to rfft bins: X[k] = Ze[k] + e^{-2pi i k/1024} * Zo[k], k = 0..512
    float2* out = g_X + (size_t)row * NBINS;
    for (int k = tid; k < NBINS; k += 128) {
        float2 Zk = Z[k & 511];
        float2 Zm = Z[(512 - k) & 511];
        // Ze = (Zk + conj(Zm))/2 ; D = Zk - conj(Zm) ; Zo = -0.5i * D
        float2 Ze = make_float2(0.5f * (Zk.x + Zm.x), 0.5f * (Zk.y - Zm.y));
        float2 D  = make_float2(Zk.x - Zm.x, Zk.y + Zm.y);
        float2 Zo = make_float2(0.5f * D.y, -0.5f * D.x);
        float2 tw = (k == 512) ? make_float2(-1.0f, 0.0f)
                               : make_float2(T[k].x, -T[k].y);
        out[k] = cadd(Ze, cmul(tw, Zo));
    }
}

// ------------- Kernel B: per (b, pair, t): PHAT cross-spectrum + 64-lag irfft -------------
__global__ __launch_bounds__(128) void xcorr_kernel(float* __restrict__ out) {
    __shared__ float2 T[512];
    __shared__ float2 Rsh[NBINS];
    __shared__ float2 bufA[512];
    __shared__ float2 bufB[512];
    int tid = threadIdx.x;
    int id = blockIdx.x;                 // ((b*28 + p)*250 + t)
    int t  = id % NT;
    int pr = (id / NT) % NPAIRS;
    int b  = id / (NT * NPAIRS);

    const float2* X1 = g_X + (((size_t)(b * NCH + c_i1[pr])) * NT + t) * NBINS;
    const float2* X2 = g_X + (((size_t)(b * NCH + c_i2[pr])) * NT + t) * NBINS;

    #pragma unroll
    for (int j = tid; j < 512; j += 128) {
        float sv, cv;
        sincospif(j * (1.0f / 512.0f), &sv, &cv);
        T[j] = make_float2(cv, sv);
    }
    for (int k = tid; k < NBINS; k += 128) {
        float2 a = X1[k];
        float2 c = X2[k];
        float pre = a.x * c.x + a.y * c.y;        // X1 * conj(X2)
        float pim = a.y * c.x - a.x * c.y;
        float mag = sqrtf(pre * pre + pim * pim);
        float inv = 1.0f / (mag + EPS_PHAT);
        Rsh[k] = make_float2(pre * inv, pim * inv);
    }
    __syncthreads();

    // Build Z[k] = Ze[k] + i*Zo[k] for the packed inverse real FFT:
    //   Ze = (R[k] + conj(R[512-k]))/2
    //   Zo = e^{+2pi i k/1024} * (R[k] - conj(R[512-k]))/2
    #pragma unroll
    for (int k = tid; k < 512; k += 128) {
        float2 Xa = Rsh[k];
        float2 Xb = Rsh[512 - k];
        float2 Ze = make_float2(0.5f * (Xa.x + Xb.x), 0.5f * (Xa.y - Xb.y));
        float2 U  = make_float2(0.5f * (Xa.x - Xb.x), 0.5f * (Xa.y + Xb.y));
        float2 Zo = cmul(T[k], U);
        bufA[k] = make_float2(Ze.x - Zo.y, Ze.y + Zo.x);
    }
    __syncthreads();

    float2* z = fft512<+1>(bufA, bufB, T, tid);

    // x[n] = irfft(R)[n]; x[2n] = Re z[n]/512, x[2n+1] = Im z[n]/512.
    // Output j (0..63) takes x[(992 + j) & 1023]  (fftshift + center slice).
    if (tid < NLAGS) {
        int idx = (992 + tid) & 1023;
        float2 zz = z[idx >> 1];
        float v = (idx & 1) ? zz.y : zz.x;
        out[(size_t)id * NLAGS + tid] = v * (1.0f / 512.0f);
    }
}

extern "C" void kernel_launch(void* const* d_in, const int* in_sizes, int n_in,
                              void* d_out, int out_size) {
    const float* x = (const float*)d_in[0];
    float* out = (float*)d_out;
    fwd_fft_kernel<<<NBATCH * NCH * NT, 128>>>(x);
    xcorr_kernel<<<NBATCH * NPAIRS * NT, 128>>>(out);
}

// round 4
// speedup vs baseline: 1.1930x; 1.1930x over previous
#include <cuda_runtime.h>
#include <cuda_bf16.h>

#define L_FFT   1024
#define NBINS   513
#define NBATCH  16
#define NCH     8
#define NT      250
#define NPAIRS  28
#define NLAGS   64
#define EPS_PHAT 1e-8f

// Scratch: spectra of all (b, m, t) rows. 16*8*250*513 complex = ~131 MB.
__device__ float2 g_X[(size_t)NBATCH * NCH * NT * NBINS];

__constant__ int c_i1[NPAIRS] = {0,0,0,0,0,0,0,1,1,1,1,1,1,2,2,2,2,2,3,3,3,3,4,4,4,5,5,6};
__constant__ int c_i2[NPAIRS] = {1,2,3,4,5,6,7,2,3,4,5,6,7,3,4,5,6,7,4,5,6,7,5,6,7,6,7,7};

__device__ __forceinline__ float2 cadd(float2 a, float2 b){ return make_float2(a.x+b.x, a.y+b.y); }
__device__ __forceinline__ float2 csub(float2 a, float2 b){ return make_float2(a.x-b.x, a.y-b.y); }
__device__ __forceinline__ float2 cmul(float2 a, float2 b){ return make_float2(a.x*b.x - a.y*b.y, a.x*b.y + a.y*b.x); }

// Bank-conflict padding: one extra float2 every 8.
#define PD(i) ((i) + ((i) >> 3))
#define ABUF  576   // PD(511) = 574, round up

// Natural-order radix-8 butterfly. S=-1: forward (e^{-2pi i/8}); S=+1: inverse.
template<int S>
__device__ __forceinline__ void bfly8(float2 v[8]) {
    const float C = 0.70710678118654752440f;
    float2 t0=cadd(v[0],v[4]), t4=csub(v[0],v[4]);
    float2 t1=cadd(v[1],v[5]), t5=csub(v[1],v[5]);
    float2 t2=cadd(v[2],v[6]), t6=csub(v[2],v[6]);
    float2 t3=cadd(v[3],v[7]), t7=csub(v[3],v[7]);
    // odd-branch pre-twiddles: t5*w8^1, t6*w8^2, t7*w8^3  (w8 = e^{S*2pi i/8})
    float2 u5 = make_float2(C*(t5.x - S*t5.y), C*(t5.y + S*t5.x));
    float2 u6 = make_float2((float)(-S)*t6.y, (float)S*t6.x);
    float2 u7 = make_float2(-C*(t7.x + S*t7.y), C*(S*t7.x - t7.y));
    // even FFT4 (w4 = S*i): outputs -> X0,X2,X4,X6
    float2 p0=cadd(t0,t2), q0=csub(t0,t2);
    float2 p1=cadd(t1,t3), q1t=csub(t1,t3);
    float2 q1 = make_float2((float)(-S)*q1t.y, (float)S*q1t.x);
    v[0]=cadd(p0,p1); v[4]=csub(p0,p1);
    v[2]=cadd(q0,q1); v[6]=csub(q0,q1);
    // odd FFT4 on (t4,u5,u6,u7): outputs -> X1,X3,X5,X7
    float2 r0=cadd(t4,u6), s0=csub(t4,u6);
    float2 r1=cadd(u5,u7), s1t=csub(u5,u7);
    float2 s1 = make_float2((float)(-S)*s1t.y, (float)S*s1t.x);
    v[1]=cadd(r0,r1); v[5]=csub(r0,r1);
    v[3]=cadd(s0,s1); v[7]=csub(s0,s1);
}

// Apply v[j] *= w^j for j=1..7, w given.
__device__ __forceinline__ void twiddle7(float2 v[8], float2 w) {
    float2 acc = w;
    v[1] = cmul(v[1], acc);
    #pragma unroll
    for (int j = 2; j < 8; j++) { acc = cmul(acc, w); v[j] = cmul(v[j], acc); }
}

// Middle passes of the 512-pt register FFT, operating in shared A (padded).
// On entry: pass-1 results already stored (slot t+64j). On exit: pass 3 done,
// v[] in registers holds Z[(t>>3) + 8*(t&7) + 64*m] for m=0..7.
template<int S>
__device__ __forceinline__ void fft512_mid(float2* A, float2 v[8], int t) {
    // ---- pass 2: blocks of 64, stride 8 ----
    int j2 = t >> 3, n3 = t & 7;
    int b2 = 64 * j2 + n3;
    #pragma unroll
    for (int l = 0; l < 8; l++) v[l] = A[PD(b2 + 8*l)];
    bfly8<S>(v);
    {
        float s, c; sincospif((float)n3 * (1.0f/32.0f), &s, &c);
        twiddle7(v, make_float2(c, (float)S * s));
    }
    #pragma unroll
    for (int l = 0; l < 8; l++) A[PD(b2 + 8*l)] = v[l];
    __syncthreads();
    // ---- pass 3: blocks of 8, stride 1, no twiddle ----
    #pragma unroll
    for (int l = 0; l < 8; l++) v[l] = A[PD(8*t + l)];
    bfly8<S>(v);
    // Z[k] now in regs: k = (t>>3) + 8*(t&7) + 64*m
}

// ---------------- Kernel A: forward rfft of each (b, m, t) row ----------------
// 64 threads per block. Real 1024-pt rfft via complex 512-pt register FFT.
__global__ __launch_bounds__(64) void fwd_fft_kernel(const float* __restrict__ x) {
    __shared__ float2 A[ABUF];
    int t = threadIdx.x;
    int row = blockIdx.x;
    const float2* xin = reinterpret_cast<const float2*>(x + (size_t)row * L_FFT);

    float2 v[8];
    // pass 1 input direct from global: z[n] = x[2n] + i x[2n+1], slots t+64l
    #pragma unroll
    for (int l = 0; l < 8; l++) v[l] = xin[t + 64*l];
    bfly8<-1>(v);
    {
        float s, c; sincospif((float)t * (1.0f/256.0f), &s, &c);
        twiddle7(v, make_float2(c, -s));
    }
    #pragma unroll
    for (int j = 0; j < 8; j++) A[PD(t + 64*j)] = v[j];
    __syncthreads();

    fft512_mid<-1>(A, v, t);
    __syncthreads();   // all pass-3 reads done before scatter overwrites
    // scatter Z to natural order in shared
    int base = (t >> 3) + 8 * (t & 7);
    #pragma unroll
    for (int m = 0; m < 8; m++) A[PD(base + 64*m)] = v[m];
    __syncthreads();

    // Unpack to rfft bins: X[k] = Ze[k] + e^{-2pi i k/1024} * Zo[k], k=0..512
    float2* out = g_X + (size_t)row * NBINS;
    for (int k = t; k < NBINS; k += 64) {
        float2 Zk = A[PD(k & 511)];
        float2 Zm = A[PD((512 - k) & 511)];
        float2 Ze = make_float2(0.5f * (Zk.x + Zm.x), 0.5f * (Zk.y - Zm.y));
        float2 D  = make_float2(Zk.x - Zm.x, Zk.y + Zm.y);
        float2 Zo = make_float2(0.5f * D.y, -0.5f * D.x);
        float s, c; sincospif((float)k * (1.0f/512.0f), &s, &c);  // k=512 -> (-1,0)
        float2 tw = make_float2(c, -s);
        out[k] = cadd(Ze, cmul(tw, Zo));
    }
}

// ------------- Kernel B: per (b, pair, t): PHAT cross-spectrum + 64-lag irfft -------------
__global__ __launch_bounds__(64) void xcorr_kernel(float* __restrict__ out) {
    __shared__ float2 A[ABUF];
    int t = threadIdx.x;
    int id = blockIdx.x;                 // ((b*28 + p)*250 + tt)
    int tt = id % NT;
    int pr = (id / NT) % NPAIRS;
    int b  = id / (NT * NPAIRS);

    const float2* X1 = g_X + (((size_t)(b * NCH + c_i1[pr])) * NT + tt) * NBINS;
    const float2* X2 = g_X + (((size_t)(b * NCH + c_i2[pr])) * NT + tt) * NBINS;

    // Build hermitian-packed Z directly into shared (pairs k, 512-k share R values).
    for (int k = t; k <= 256; k += 64) {
        int km = 512 - k;
        float2 a1 = X1[k],  c1 = X2[k];
        float2 a2 = X1[km], c2 = X2[km];
        float reA = a1.x*c1.x + a1.y*c1.y, imA = a1.y*c1.x - a1.x*c1.y;
        float reB = a2.x*c2.x + a2.y*c2.y, imB = a2.y*c2.x - a2.x*c2.y;
        float invA = 1.0f / (sqrtf(reA*reA + imA*imA) + EPS_PHAT);
        float invB = 1.0f / (sqrtf(reB*reB + imB*imB) + EPS_PHAT);
        float2 Ra = make_float2(reA*invA, imA*invA);
        float2 Rb = make_float2(reB*invB, imB*invB);
        float s, c; sincospif((float)k * (1.0f/512.0f), &s, &c);  // T_k = e^{+2pi i k/1024}
        // Z[k] from (Ra, Rb) with T=(c,s)
        {
            float2 Ze = make_float2(0.5f*(Ra.x + Rb.x), 0.5f*(Ra.y - Rb.y));
            float2 U  = make_float2(0.5f*(Ra.x - Rb.x), 0.5f*(Ra.y + Rb.y));
            float2 Zo = cmul(make_float2(c, s), U);
            A[PD(k)] = make_float2(Ze.x - Zo.y, Ze.y + Zo.x);
        }
        if (k > 0 && k < 256) {
            // Z[512-k] from (Rb, Ra) with T_{512-k} = (-c, s)
            float2 Ze = make_float2(0.5f*(Rb.x + Ra.x), 0.5f*(Rb.y - Ra.y));
            float2 U  = make_float2(0.5f*(Rb.x - Ra.x), 0.5f*(Rb.y + Ra.y));
            float2 Zo = cmul(make_float2(-c, s), U);
            A[PD(km)] = make_float2(Ze.x - Zo.y, Ze.y + Zo.x);
        }
    }
    __syncthreads();

    float2 v[8];
    // pass 1 (inverse): slots t+64l
    #pragma unroll
    for (int l = 0; l < 8; l++) v[l] = A[PD(t + 64*l)];
    bfly8<1>(v);
    {
        float s, c; sincospif((float)t * (1.0f/256.0f), &s, &c);
        twiddle7(v, make_float2(c, s));
    }
    #pragma unroll
    for (int j = 0; j < 8; j++) A[PD(t + 64*j)] = v[j];
    __syncthreads();

    fft512_mid<1>(A, v, t);

    // Thread t reg m holds z[n], n = base + 64m, base = (t>>3)+8*(t&7).
    // Need n in [0,16) (m=0) and [496,512) (m=7); x[2n]=Re z/512, x[2n+1]=Im z/512.
    // Output j takes cc[(992+j)&1023].
    int base = (t >> 3) + 8 * (t & 7);
    const float sc = 1.0f / 512.0f;
    float2* orow = reinterpret_cast<float2*>(out + (size_t)id * NLAGS);
    if (base < 16) {
        float2 z = v[0];                       // n = base, idx = 2n in [0,32) -> j = idx+32
        orow[(32 + 2*base) >> 1] = make_float2(z.x * sc, z.y * sc);
    }
    if (base >= 48) {
        float2 z = v[7];                       // n = base+448 in [496,512), j = 2n-992
        int j = 2*(base + 448) - 992;
        orow[j >> 1] = make_float2(z.x * sc, z.y * sc);
    }
}

extern "C" void kernel_launch(void* const* d_in, const int* in_sizes, int n_in,
                              void* d_out, int out_size) {
    const float* x = (const float*)d_in[0];
    float* out = (float*)d_out;
    fwd_fft_kernel<<<NBATCH * NCH * NT, 64>>>(x);
    xcorr_kernel<<<NBATCH * NPAIRS * NT, 64>>>(out);
}

// round 5
// speedup vs baseline: 2.7316x; 2.2896x over previous
#include <cuda_runtime.h>
#include <cuda_bf16.h>

#define L_FFT   1024
#define NBINS   513
#define NBATCH  16
#define NCH     8
#define NT      250
#define NPAIRS  28
#define NLAGS   64

typedef unsigned long long ull;

// Scratch: PHASE-NORMALIZED spectra of all (b, m, t) rows. ~131 MB.
__device__ float2 g_X[(size_t)NBATCH * NCH * NT * NBINS];

__constant__ int c_i1[NPAIRS] = {0,0,0,0,0,0,0,1,1,1,1,1,1,2,2,2,2,2,3,3,3,3,4,4,4,5,5,6};
__constant__ int c_i2[NPAIRS] = {1,2,3,4,5,6,7,2,3,4,5,6,7,3,4,5,6,7,4,5,6,7,5,6,7,6,7,7};

// Pass-2 twiddle LUT: e^{2 pi i j / 64}, j = 0..7
__constant__ float2 c_w64[8] = {
    {1.0f, 0.0f},
    {0.99518472667219689f, 0.09801714032956060f},
    {0.98078528040323045f, 0.19509032201612827f},
    {0.95694033573220887f, 0.29028467725446234f},
    {0.92387953251128676f, 0.38268343236508977f},
    {0.88192126434835503f, 0.47139673682599764f},
    {0.83146961230254524f, 0.55557023301960222f},
    {0.77301045336273696f, 0.63439328416364549f}
};

union C64u { float2 f; ull u; };
__device__ __forceinline__ ull   F2U(float2 a){ C64u c; c.f=a; return c.u; }
__device__ __forceinline__ float2 U2F(ull a){ C64u c; c.u=a; return c.f; }

// Packed f32x2 ops (sm_100+): one instruction per complex add/sub.
__device__ __forceinline__ ull padd(ull a, ull b){ ull r; asm("add.rn.f32x2 %0,%1,%2;" : "=l"(r) : "l"(a), "l"(b)); return r; }
__device__ __forceinline__ ull psub(ull a, ull b){ ull r; asm("sub.rn.f32x2 %0,%1,%2;" : "=l"(r) : "l"(a), "l"(b)); return r; }
__device__ __forceinline__ ull pmulp(ull a, ull b){ ull r; asm("mul.rn.f32x2 %0,%1,%2;" : "=l"(r) : "l"(a), "l"(b)); return r; }

__device__ __forceinline__ float2 cadd(float2 a, float2 b){ return make_float2(a.x+b.x, a.y+b.y); }
__device__ __forceinline__ float2 cmul(float2 a, float2 b){ return make_float2(a.x*b.x - a.y*b.y, a.x*b.y + a.y*b.x); }

// multiply by S*i  (S=+1: i, S=-1: -i)
template<int S>
__device__ __forceinline__ ull muli(ull a){
    float2 f = U2F(a);
    return F2U(S > 0 ? make_float2(-f.y, f.x) : make_float2(f.y, -f.x));
}

// Bank-conflict padding: one extra float2 every 8.
#define PD(i) ((i) + ((i) >> 3))
#define ABUF  576

// Natural-order radix-8 butterfly on packed complexes. S=-1 fwd, S=+1 inv.
template<int S>
__device__ __forceinline__ void pbfly8(ull v[8]) {
    const float Cc = 0.70710678118654752440f;
    const ull CC = F2U(make_float2(Cc, Cc));
    ull t0 = padd(v[0], v[4]), t4 = psub(v[0], v[4]);
    ull t1 = padd(v[1], v[5]), t5 = psub(v[1], v[5]);
    ull t2 = padd(v[2], v[6]), t6 = psub(v[2], v[6]);
    ull t3 = padd(v[3], v[7]), t7 = psub(v[3], v[7]);
    // odd pre-twiddles: w8^1 = C(1+Si), w8^2 = Si, w8^3 = C(-1+Si)
    ull u5 = pmulp(CC, padd(t5, muli<S>(t5)));
    ull u6 = muli<S>(t6);
    ull u7 = pmulp(CC, psub(muli<S>(t7), t7));
    // even FFT4 -> X0,X2,X4,X6
    ull p0 = padd(t0, t2), q0 = psub(t0, t2);
    ull p1 = padd(t1, t3), q1 = muli<S>(psub(t1, t3));
    v[0] = padd(p0, p1); v[4] = psub(p0, p1);
    v[2] = padd(q0, q1); v[6] = psub(q0, q1);
    // odd FFT4 -> X1,X3,X5,X7
    ull r0 = padd(t4, u6), s0 = psub(t4, u6);
    ull r1 = padd(u5, u7), s1 = muli<S>(psub(u5, u7));
    v[1] = padd(r0, r1); v[5] = psub(r0, r1);
    v[3] = padd(s0, s1); v[7] = psub(s0, s1);
}

// v[j] *= w^j, j=1..7 (shallow power tree).
__device__ __forceinline__ void twiddle7(ull v[8], float2 w){
    float2 w2 = cmul(w,  w);
    float2 w3 = cmul(w2, w);
    float2 w4 = cmul(w2, w2);
    float2 w5 = cmul(w3, w2);
    float2 w6 = cmul(w3, w3);
    float2 w7 = cmul(w4, w3);
    v[1] = F2U(cmul(U2F(v[1]), w));
    v[2] = F2U(cmul(U2F(v[2]), w2));
    v[3] = F2U(cmul(U2F(v[3]), w3));
    v[4] = F2U(cmul(U2F(v[4]), w4));
    v[5] = F2U(cmul(U2F(v[5]), w5));
    v[6] = F2U(cmul(U2F(v[6]), w6));
    v[7] = F2U(cmul(U2F(v[7]), w7));
}

// Passes 2+3 of the 512-pt register FFT. On entry A holds pass-1 results
// (slot t+64j). On exit v[] holds Z[(t>>3) + 8*(t&7) + 64*m].
template<int S>
__device__ __forceinline__ void fft_mid(float2* A, ull v[8], int t){
    int n3 = t & 7;
    int b2 = 64 * (t >> 3) + n3;
    #pragma unroll
    for (int l = 0; l < 8; l++) v[l] = F2U(A[PD(b2 + 8*l)]);
    pbfly8<S>(v);
    {
        float2 w = c_w64[n3];
        twiddle7(v, S > 0 ? w : make_float2(w.x, -w.y));
    }
    #pragma unroll
    for (int l = 0; l < 8; l++) A[PD(b2 + 8*l)] = U2F(v[l]);
    __syncthreads();
    #pragma unroll
    for (int l = 0; l < 8; l++) v[l] = F2U(A[PD(8*t + l)]);
    pbfly8<S>(v);
}

// ---------------- Kernel A: forward rfft + PHAT phase-normalize ----------------
__global__ __launch_bounds__(64) void fwd_fft_kernel(const float* __restrict__ x) {
    __shared__ float2 A[ABUF];
    int t = threadIdx.x;
    int row = blockIdx.x;
    const float2* xin = reinterpret_cast<const float2*>(x + (size_t)row * L_FFT);

    float sT, cT; sincospif((float)t * (1.0f/512.0f), &sT, &cT);  // T_t = e^{2pi i t/1024}
    float2 Tt = make_float2(cT, sT);

    ull v[8];
    #pragma unroll
    for (int l = 0; l < 8; l++) v[l] = F2U(xin[t + 64*l]);
    pbfly8<-1>(v);
    {
        float2 T2 = cmul(Tt, Tt);                  // e^{2pi i t/512}
        twiddle7(v, make_float2(T2.x, -T2.y));     // conj for forward
    }
    #pragma unroll
    for (int j = 0; j < 8; j++) A[PD(t + 64*j)] = U2F(v[j]);
    __syncthreads();

    fft_mid<-1>(A, v, t);
    __syncthreads();
    int base = (t >> 3) + 8 * (t & 7);
    #pragma unroll
    for (int m = 0; m < 8; m++) A[PD(base + 64*m)] = U2F(v[m]);
    __syncthreads();

    // Unpack + normalize: U[k] = X[k]/|X[k]|, X[k] = Ze + e^{-2pi i k/1024} Zo
    float2* outp = g_X + (size_t)row * NBINS;
    const float2 W64t = make_float2(0.92387953251128676f, 0.38268343236508977f); // e^{i pi/8}
    float2 Tk = Tt;
    #pragma unroll
    for (int i = 0; i < 8; i++) {
        int k = t + 64*i;
        float2 Zk = A[PD(k)];
        float2 Zm = A[PD((512 - k) & 511)];
        float2 Ze = make_float2(0.5f * (Zk.x + Zm.x), 0.5f * (Zk.y - Zm.y));
        float2 D  = make_float2(Zk.x - Zm.x, Zk.y + Zm.y);
        float2 Zo = make_float2(0.5f * D.y, -0.5f * D.x);
        float2 tw = make_float2(Tk.x, -Tk.y);
        float2 X  = cadd(Ze, cmul(tw, Zo));
        float inv = rsqrtf(fmaxf(X.x*X.x + X.y*X.y, 1e-30f));
        outp[k] = make_float2(X.x * inv, X.y * inv);
        Tk = cmul(Tk, W64t);
    }
    if (t == 0) {   // bin 512: X = Z0.x - Z0.y (real)
        float2 Z0 = A[PD(0)];
        float Xr = Z0.x - Z0.y;
        float inv = rsqrtf(fmaxf(Xr*Xr, 1e-30f));
        outp[512] = make_float2(Xr * inv, 0.0f);
    }
}

// ------------- Kernel B: cross-phase + 64-lag inverse real FFT -------------
__global__ __launch_bounds__(64) void xcorr_kernel(float* __restrict__ out) {
    __shared__ float2 A[ABUF];
    int t = threadIdx.x;
    int id = blockIdx.x;                 // ((b*28 + p)*250 + tt)
    int tt = id % NT;
    int pr = (id / NT) % NPAIRS;
    int b  = id / (NT * NPAIRS);

    const float2* X1 = g_X + (((size_t)(b * NCH + c_i1[pr])) * NT + tt) * NBINS;
    const float2* X2 = g_X + (((size_t)(b * NCH + c_i2[pr])) * NT + tt) * NBINS;

    float sT, cT; sincospif((float)t * (1.0f/512.0f), &sT, &cT);
    float2 Tt = make_float2(cT, sT);
    const float2 W64t = make_float2(0.92387953251128676f, 0.38268343236508977f);

    // Hermitian-packed Z built directly into shared. R[k] = U1[k]*conj(U2[k])
    // (already unit magnitude — no sqrt/div here).
    float2 Tk = Tt;
    #pragma unroll
    for (int i = 0; i < 4; i++) {
        int k  = t + 64*i;          // k in [0,256)
        int km = 512 - k;
        float2 a1 = X1[k],  c1 = X2[k];
        float2 a2 = X1[km], c2 = X2[km];
        float2 Ra = make_float2(a1.x*c1.x + a1.y*c1.y, a1.y*c1.x - a1.x*c1.y);
        float2 Rb = make_float2(a2.x*c2.x + a2.y*c2.y, a2.y*c2.x - a2.x*c2.y);
        // Z[k] from (Ra, Rb) with T_k
        float2 Ze = make_float2(0.5f*(Ra.x + Rb.x), 0.5f*(Ra.y - Rb.y));
        float2 U  = make_float2(0.5f*(Ra.x - Rb.x), 0.5f*(Ra.y + Rb.y));
        float2 Zo = cmul(Tk, U);
        A[PD(k)] = make_float2(Ze.x - Zo.y, Ze.y + Zo.x);
        if (k > 0) {
            // Z[512-k] from (Rb, Ra) with T_{512-k} = (-Tk.x, Tk.y)
            float2 Ze2 = make_float2(0.5f*(Rb.x + Ra.x), 0.5f*(Rb.y - Ra.y));
            float2 U2  = make_float2(0.5f*(Rb.x - Ra.x), 0.5f*(Rb.y + Ra.y));
            float2 Zo2 = cmul(make_float2(-Tk.x, Tk.y), U2);
            A[PD(km)] = make_float2(Ze2.x - Zo2.y, Ze2.y + Zo2.x);
        }
        Tk = cmul(Tk, W64t);
    }
    if (t == 0) {   // Z[256] = conj(R[256])
        float2 a = X1[256], c = X2[256];
        A[PD(256)] = make_float2(a.x*c.x + a.y*c.y, -(a.y*c.x - a.x*c.y));
    }
    __syncthreads();

    ull v[8];
    #pragma unroll
    for (int l = 0; l < 8; l++) v[l] = F2U(A[PD(t + 64*l)]);
    pbfly8<1>(v);
    {
        float2 T2 = cmul(Tt, Tt);   // e^{+2pi i t/512}
        twiddle7(v, T2);
    }
    #pragma unroll
    for (int j = 0; j < 8; j++) A[PD(t + 64*j)] = U2F(v[j]);
    __syncthreads();

    fft_mid<1>(A, v, t);

    // Thread t reg m holds z[n], n = base + 64m, base = (t>>3)+8*(t&7).
    // x[2n] = Re z/512, x[2n+1] = Im z/512; output j takes cc[(992+j)&1023].
    int base = (t >> 3) + 8 * (t & 7);
    const float sc = 1.0f / 512.0f;
    float2* orow = reinterpret_cast<float2*>(out + (size_t)id * NLAGS);
    if (base < 16) {
        float2 z = U2F(v[0]);                  // n = base -> j = 2n+32
        orow[(32 + 2*base) >> 1] = make_float2(z.x * sc, z.y * sc);
    }
    if (base >= 48) {
        float2 z = U2F(v[7]);                  // n = base+448 -> j = 2n-992
        int j = 2*(base + 448) - 992;
        orow[j >> 1] = make_float2(z.x * sc, z.y * sc);
    }
}

extern "C" void kernel_launch(void* const* d_in, const int* in_sizes, int n_in,
                              void* d_out, int out_size) {
    const float* x = (const float*)d_in[0];
    float* out = (float*)d_out;
    fwd_fft_kernel<<<NBATCH * NCH * NT, 64>>>(x);
    xcorr_kernel<<<NBATCH * NPAIRS * NT, 64>>>(out);
}

// round 6
// speedup vs baseline: 2.9281x; 1.0719x over previous
#include <cuda_runtime.h>
#include <cuda_bf16.h>

#define L_FFT   1024
#define NBINS   513
#define NBATCH  16
#define NCH     8
#define NT      250
#define NPAIRS  28
#define NLAGS   64

typedef unsigned long long ull;

// Scratch: PHASE-NORMALIZED spectra of all (b, m, t) rows. ~131 MB.
__device__ float2 g_X[(size_t)NBATCH * NCH * NT * NBINS];

__constant__ int c_i1[NPAIRS] = {0,0,0,0,0,0,0,1,1,1,1,1,1,2,2,2,2,2,3,3,3,3,4,4,4,5,5,6};
__constant__ int c_i2[NPAIRS] = {1,2,3,4,5,6,7,2,3,4,5,6,7,3,4,5,6,7,4,5,6,7,5,6,7,6,7,7};

// Pass-2 twiddle LUT: e^{2 pi i j / 64}, j = 0..7
__constant__ float2 c_w64[8] = {
    {1.0f, 0.0f},
    {0.99518472667219689f, 0.09801714032956060f},
    {0.98078528040323045f, 0.19509032201612827f},
    {0.95694033573220887f, 0.29028467725446234f},
    {0.92387953251128676f, 0.38268343236508977f},
    {0.88192126434835503f, 0.47139673682599764f},
    {0.83146961230254524f, 0.55557023301960222f},
    {0.77301045336273696f, 0.63439328416364549f}
};

union C64u { float2 f; ull u; };
__device__ __forceinline__ ull   F2U(float2 a){ C64u c; c.f=a; return c.u; }
__device__ __forceinline__ float2 U2F(ull a){ C64u c; c.u=a; return c.f; }

// Packed f32x2 ops (sm_100+): one instruction per complex add/sub.
__device__ __forceinline__ ull padd(ull a, ull b){ ull r; asm("add.rn.f32x2 %0,%1,%2;" : "=l"(r) : "l"(a), "l"(b)); return r; }
__device__ __forceinline__ ull psub(ull a, ull b){ ull r; asm("sub.rn.f32x2 %0,%1,%2;" : "=l"(r) : "l"(a), "l"(b)); return r; }
__device__ __forceinline__ ull pmulp(ull a, ull b){ ull r; asm("mul.rn.f32x2 %0,%1,%2;" : "=l"(r) : "l"(a), "l"(b)); return r; }

__device__ __forceinline__ float2 cadd(float2 a, float2 b){ return make_float2(a.x+b.x, a.y+b.y); }
__device__ __forceinline__ float2 cmul(float2 a, float2 b){ return make_float2(a.x*b.x - a.y*b.y, a.x*b.y + a.y*b.x); }

// multiply by S*i  (S=+1: i, S=-1: -i)
template<int S>
__device__ __forceinline__ ull muli(ull a){
    float2 f = U2F(a);
    return F2U(S > 0 ? make_float2(-f.y, f.x) : make_float2(f.y, -f.x));
}

// Bank-conflict padding: one extra float2 every 8.
#define PD(i) ((i) + ((i) >> 3))
#define ABUF  576

// Natural-order radix-8 butterfly on packed complexes. S=-1 fwd, S=+1 inv.
template<int S>
__device__ __forceinline__ void pbfly8(ull v[8]) {
    const float Cc = 0.70710678118654752440f;
    const ull CC = F2U(make_float2(Cc, Cc));
    ull t0 = padd(v[0], v[4]), t4 = psub(v[0], v[4]);
    ull t1 = padd(v[1], v[5]), t5 = psub(v[1], v[5]);
    ull t2 = padd(v[2], v[6]), t6 = psub(v[2], v[6]);
    ull t3 = padd(v[3], v[7]), t7 = psub(v[3], v[7]);
    ull u5 = pmulp(CC, padd(t5, muli<S>(t5)));
    ull u6 = muli<S>(t6);
    ull u7 = pmulp(CC, psub(muli<S>(t7), t7));
    ull p0 = padd(t0, t2), q0 = psub(t0, t2);
    ull p1 = padd(t1, t3), q1 = muli<S>(psub(t1, t3));
    v[0] = padd(p0, p1); v[4] = psub(p0, p1);
    v[2] = padd(q0, q1); v[6] = psub(q0, q1);
    ull r0 = padd(t4, u6), s0 = psub(t4, u6);
    ull r1 = padd(u5, u7), s1 = muli<S>(psub(u5, u7));
    v[1] = padd(r0, r1); v[5] = psub(r0, r1);
    v[3] = padd(s0, s1); v[7] = psub(s0, s1);
}

// v[j] *= w^j, j=1..7 (shallow power tree).
__device__ __forceinline__ void twiddle7(ull v[8], float2 w){
    float2 w2 = cmul(w,  w);
    float2 w3 = cmul(w2, w);
    float2 w4 = cmul(w2, w2);
    float2 w5 = cmul(w3, w2);
    float2 w6 = cmul(w3, w3);
    float2 w7 = cmul(w4, w3);
    v[1] = F2U(cmul(U2F(v[1]), w));
    v[2] = F2U(cmul(U2F(v[2]), w2));
    v[3] = F2U(cmul(U2F(v[3]), w3));
    v[4] = F2U(cmul(U2F(v[4]), w4));
    v[5] = F2U(cmul(U2F(v[5]), w5));
    v[6] = F2U(cmul(U2F(v[6]), w6));
    v[7] = F2U(cmul(U2F(v[7]), w7));
}

// Passes 2+3 of the 512-pt register FFT. On entry A holds pass-1 results
// (slot t+64j). On exit v[] holds Z[(t>>3) + 8*(t&7) + 64*m].
template<int S>
__device__ __forceinline__ void fft_mid(float2* A, ull v[8], int t){
    int n3 = t & 7;
    int b2 = 64 * (t >> 3) + n3;
    #pragma unroll
    for (int l = 0; l < 8; l++) v[l] = F2U(A[PD(b2 + 8*l)]);
    pbfly8<S>(v);
    {
        float2 w = c_w64[n3];
        twiddle7(v, S > 0 ? w : make_float2(w.x, -w.y));
    }
    #pragma unroll
    for (int l = 0; l < 8; l++) A[PD(b2 + 8*l)] = U2F(v[l]);
    __syncthreads();
    #pragma unroll
    for (int l = 0; l < 8; l++) v[l] = F2U(A[PD(8*t + l)]);
    pbfly8<S>(v);
}

// ---------------- Kernel A: forward rfft + PHAT phase-normalize ----------------
__global__ __launch_bounds__(64) void fwd_fft_kernel(const float* __restrict__ x) {
    __shared__ float2 A[ABUF];
    int t = threadIdx.x;
    int row = blockIdx.x;
    const float2* xin = reinterpret_cast<const float2*>(x + (size_t)row * L_FFT);

    float sT, cT; sincospif((float)t * (1.0f/512.0f), &sT, &cT);  // T_t = e^{2pi i t/1024}
    float2 Tt = make_float2(cT, sT);

    ull v[8];
    #pragma unroll
    for (int l = 0; l < 8; l++) v[l] = F2U(xin[t + 64*l]);
    pbfly8<-1>(v);
    {
        float2 T2 = cmul(Tt, Tt);                  // e^{2pi i t/512}
        twiddle7(v, make_float2(T2.x, -T2.y));     // conj for forward
    }
    #pragma unroll
    for (int j = 0; j < 8; j++) A[PD(t + 64*j)] = U2F(v[j]);
    __syncthreads();

    fft_mid<-1>(A, v, t);
    __syncthreads();   // all pass-3 reads done before scatter overwrites
    // scatter Z to natural order (needed only for cross-thread mirror reads)
    int base = (t >> 3) + 8 * (t & 7);
    #pragma unroll
    for (int m = 0; m < 8; m++) A[PD(base + 64*m)] = U2F(v[m]);
    __syncthreads();

    // Unpack + normalize. Thread t outputs bins k = base + 64m; Zk comes from
    // registers (v[m]), only the mirror Zm is read from shared.
    float2* outp = g_X + (size_t)row * NBINS;
    const float2 W64t = make_float2(0.92387953251128676f, 0.38268343236508977f); // e^{i pi/8}
    float sB, cB; sincospif((float)base * (1.0f/512.0f), &sB, &cB);
    float2 Tk = make_float2(cB, sB);               // e^{2pi i base/1024}
    #pragma unroll
    for (int m = 0; m < 8; m++) {
        int k = base + 64*m;
        float2 Zk = U2F(v[m]);
        float2 Zm = A[PD((512 - k) & 511)];
        float2 Ze = make_float2(0.5f * (Zk.x + Zm.x), 0.5f * (Zk.y - Zm.y));
        float2 D  = make_float2(Zk.x - Zm.x, Zk.y + Zm.y);
        float2 Zo = make_float2(0.5f * D.y, -0.5f * D.x);
        float2 tw = make_float2(Tk.x, -Tk.y);
        float2 X  = cadd(Ze, cmul(tw, Zo));
        float inv = rsqrtf(fmaxf(X.x*X.x + X.y*X.y, 1e-30f));
        outp[k] = make_float2(X.x * inv, X.y * inv);
        Tk = cmul(Tk, W64t);
    }
    if (t == 0) {   // base == 0: bin 512 is X = Z0.x - Z0.y (real), Z0 = v[0]
        float2 Z0 = U2F(v[0]);
        float Xr = Z0.x - Z0.y;
        float inv = rsqrtf(fmaxf(Xr*Xr, 1e-30f));
        outp[512] = make_float2(Xr * inv, 0.0f);
    }
}

// ------------- Kernel B: cross-phase + 64-lag inverse real FFT -------------
__global__ __launch_bounds__(64) void xcorr_kernel(float* __restrict__ out) {
    __shared__ float2 A[ABUF];
    int t = threadIdx.x;
    int id = blockIdx.x;                 // ((b*28 + p)*250 + tt)
    int tt = id % NT;
    int pr = (id / NT) % NPAIRS;
    int b  = id / (NT * NPAIRS);

    const float2* X1 = g_X + (((size_t)(b * NCH + c_i1[pr])) * NT + tt) * NBINS;
    const float2* X2 = g_X + (((size_t)(b * NCH + c_i2[pr])) * NT + tt) * NBINS;

    float sT, cT; sincospif((float)t * (1.0f/512.0f), &sT, &cT);
    float2 Tt = make_float2(cT, sT);
    const float2 W64t = make_float2(0.92387953251128676f, 0.38268343236508977f);

    // Partner-exchange Z-build: thread t's pass-1 slots are k = t+64i.
    // It computes Z[k] for i=0..3 itself (keeps in regs v[0..3]); the mirror
    // Z[512-k] belongs to thread 64-t (regs 7-i) and goes through shared.
    ull v[8];
    float2 Tk = Tt;
    #pragma unroll
    for (int i = 0; i < 4; i++) {
        int k  = t + 64*i;          // k in [0,256)
        int km = 512 - k;
        float2 a1 = X1[k],  c1 = X2[k];
        float2 a2 = X1[km], c2 = X2[km];
        float2 Ra = make_float2(a1.x*c1.x + a1.y*c1.y, a1.y*c1.x - a1.x*c1.y);
        float2 Rb = make_float2(a2.x*c2.x + a2.y*c2.y, a2.y*c2.x - a2.x*c2.y);
        // Z[k] from (Ra, Rb) with T_k  -> own register
        float2 Ze = make_float2(0.5f*(Ra.x + Rb.x), 0.5f*(Ra.y - Rb.y));
        float2 U  = make_float2(0.5f*(Ra.x - Rb.x), 0.5f*(Ra.y + Rb.y));
        float2 Zo = cmul(Tk, U);
        v[i] = F2U(make_float2(Ze.x - Zo.y, Ze.y + Zo.x));
        if (k > 0) {
            // Z[512-k] from (Rb, Ra) with T_{512-k} = (-Tk.x, Tk.y) -> partner
            float2 Ze2 = make_float2(0.5f*(Rb.x + Ra.x), 0.5f*(Rb.y - Ra.y));
            float2 U2  = make_float2(0.5f*(Rb.x - Ra.x), 0.5f*(Rb.y + Ra.y));
            float2 Zo2 = cmul(make_float2(-Tk.x, Tk.y), U2);
            A[PD(km)] = make_float2(Ze2.x - Zo2.y, Ze2.y + Zo2.x);
        }
        Tk = cmul(Tk, W64t);
    }
    if (t == 0) {   // slot 256: Z[256] = conj(R[256])
        float2 a = X1[256], c = X2[256];
        A[PD(256)] = make_float2(a.x*c.x + a.y*c.y, -(a.y*c.x - a.x*c.y));
    }
    __syncthreads();
    #pragma unroll
    for (int i = 4; i < 8; i++) v[i] = F2U(A[PD(t + 64*i)]);

    pbfly8<1>(v);
    {
        float2 T2 = cmul(Tt, Tt);   // e^{+2pi i t/512}
        twiddle7(v, T2);
    }
    __syncthreads();   // partner loads complete before pass-1 stores overwrite
    #pragma unroll
    for (int j = 0; j < 8; j++) A[PD(t + 64*j)] = U2F(v[j]);
    __syncthreads();

    fft_mid<1>(A, v, t);

    // Thread t reg m holds z[n], n = base + 64m, base = (t>>3)+8*(t&7).
    // x[2n] = Re z/512, x[2n+1] = Im z/512; output j takes cc[(992+j)&1023].
    int base = (t >> 3) + 8 * (t & 7);
    const float sc = 1.0f / 512.0f;
    float2* orow = reinterpret_cast<float2*>(out + (size_t)id * NLAGS);
    if (base < 16) {
        float2 z = U2F(v[0]);                  // n = base -> j = 2n+32
        orow[(32 + 2*base) >> 1] = make_float2(z.x * sc, z.y * sc);
    }
    if (base >= 48) {
        float2 z = U2F(v[7]);                  // n = base+448 -> j = 2n-992
        int j = 2*(base + 448) - 992;
        orow[j >> 1] = make_float2(z.x * sc, z.y * sc);
    }
}

extern "C" void kernel_launch(void* const* d_in, const int* in_sizes, int n_in,
                              void* d_out, int out_size) {
    const float* x = (const float*)d_in[0];
    float* out = (float*)d_out;
    fwd_fft_kernel<<<NBATCH * NCH * NT, 64>>>(x);
    xcorr_kernel<<<NBATCH * NPAIRS * NT, 64>>>(out);
}

// round 7
// speedup vs baseline: 3.0029x; 1.0255x over previous
#include <cuda_runtime.h>
#include <cuda_bf16.h>

#define L_FFT   1024
#define NBINS   513
#define NBATCH  16
#define NCH     8
#define NT      250
#define NPAIRS  28
#define NLAGS   64

typedef unsigned long long ull;

// Scratch: PHASE-NORMALIZED spectra of all (b, m, t) rows. ~131 MB.
__device__ float2 g_X[(size_t)NBATCH * NCH * NT * NBINS];

__constant__ int c_i1[NPAIRS] = {0,0,0,0,0,0,0,1,1,1,1,1,1,2,2,2,2,2,3,3,3,3,4,4,4,5,5,6};
__constant__ int c_i2[NPAIRS] = {1,2,3,4,5,6,7,2,3,4,5,6,7,3,4,5,6,7,4,5,6,7,5,6,7,6,7,7};

// Pass-2 twiddle LUT: e^{2 pi i j / 64}, j = 0..7
__constant__ float2 c_w64[8] = {
    {1.0f, 0.0f},
    {0.99518472667219689f, 0.09801714032956060f},
    {0.98078528040323045f, 0.19509032201612827f},
    {0.95694033573220887f, 0.29028467725446234f},
    {0.92387953251128676f, 0.38268343236508977f},
    {0.88192126434835503f, 0.47139673682599764f},
    {0.83146961230254524f, 0.55557023301960222f},
    {0.77301045336273696f, 0.63439328416364549f}
};

union C64u { float2 f; ull u; };
__device__ __forceinline__ ull   F2U(float2 a){ C64u c; c.f=a; return c.u; }
__device__ __forceinline__ float2 U2F(ull a){ C64u c; c.u=a; return c.f; }

// Packed f32x2 ops (sm_100+): one instruction per complex add/sub.
__device__ __forceinline__ ull padd(ull a, ull b){ ull r; asm("add.rn.f32x2 %0,%1,%2;" : "=l"(r) : "l"(a), "l"(b)); return r; }
__device__ __forceinline__ ull psub(ull a, ull b){ ull r; asm("sub.rn.f32x2 %0,%1,%2;" : "=l"(r) : "l"(a), "l"(b)); return r; }
__device__ __forceinline__ ull pmulp(ull a, ull b){ ull r; asm("mul.rn.f32x2 %0,%1,%2;" : "=l"(r) : "l"(a), "l"(b)); return r; }

__device__ __forceinline__ float2 cadd(float2 a, float2 b){ return make_float2(a.x+b.x, a.y+b.y); }
__device__ __forceinline__ float2 cmul(float2 a, float2 b){ return make_float2(a.x*b.x - a.y*b.y, a.x*b.y + a.y*b.x); }

// multiply by S*i  (S=+1: i, S=-1: -i)
template<int S>
__device__ __forceinline__ ull muli(ull a){
    float2 f = U2F(a);
    return F2U(S > 0 ? make_float2(-f.y, f.x) : make_float2(f.y, -f.x));
}

// Bank-conflict padding: one extra float2 every 8.
#define PD(i) ((i) + ((i) >> 3))
#define ABUF  576

// Natural-order radix-8 butterfly on packed complexes. S=-1 fwd, S=+1 inv.
template<int S>
__device__ __forceinline__ void pbfly8(ull v[8]) {
    const float Cc = 0.70710678118654752440f;
    const ull CC = F2U(make_float2(Cc, Cc));
    ull t0 = padd(v[0], v[4]), t4 = psub(v[0], v[4]);
    ull t1 = padd(v[1], v[5]), t5 = psub(v[1], v[5]);
    ull t2 = padd(v[2], v[6]), t6 = psub(v[2], v[6]);
    ull t3 = padd(v[3], v[7]), t7 = psub(v[3], v[7]);
    ull u5 = pmulp(CC, padd(t5, muli<S>(t5)));
    ull u6 = muli<S>(t6);
    ull u7 = pmulp(CC, psub(muli<S>(t7), t7));
    ull p0 = padd(t0, t2), q0 = psub(t0, t2);
    ull p1 = padd(t1, t3), q1 = muli<S>(psub(t1, t3));
    v[0] = padd(p0, p1); v[4] = psub(p0, p1);
    v[2] = padd(q0, q1); v[6] = psub(q0, q1);
    ull r0 = padd(t4, u6), s0 = psub(t4, u6);
    ull r1 = padd(u5, u7), s1 = muli<S>(psub(u5, u7));
    v[1] = padd(r0, r1); v[5] = psub(r0, r1);
    v[3] = padd(s0, s1); v[7] = psub(s0, s1);
}

// v[j] *= w^j, j=1..7 (shallow power tree).
__device__ __forceinline__ void twiddle7(ull v[8], float2 w){
    float2 w2 = cmul(w,  w);
    float2 w3 = cmul(w2, w);
    float2 w4 = cmul(w2, w2);
    float2 w5 = cmul(w3, w2);
    float2 w6 = cmul(w3, w3);
    float2 w7 = cmul(w4, w3);
    v[1] = F2U(cmul(U2F(v[1]), w));
    v[2] = F2U(cmul(U2F(v[2]), w2));
    v[3] = F2U(cmul(U2F(v[3]), w3));
    v[4] = F2U(cmul(U2F(v[4]), w4));
    v[5] = F2U(cmul(U2F(v[5]), w5));
    v[6] = F2U(cmul(U2F(v[6]), w6));
    v[7] = F2U(cmul(U2F(v[7]), w7));
}

// Passes 2+3 of the 512-pt register FFT (full version, used by fwd kernel).
template<int S>
__device__ __forceinline__ void fft_mid(float2* A, ull v[8], int t){
    int n3 = t & 7;
    int b2 = 64 * (t >> 3) + n3;
    #pragma unroll
    for (int l = 0; l < 8; l++) v[l] = F2U(A[PD(b2 + 8*l)]);
    pbfly8<S>(v);
    {
        float2 w = c_w64[n3];
        twiddle7(v, S > 0 ? w : make_float2(w.x, -w.y));
    }
    #pragma unroll
    for (int l = 0; l < 8; l++) A[PD(b2 + 8*l)] = U2F(v[l]);
    __syncthreads();
    #pragma unroll
    for (int l = 0; l < 8; l++) v[l] = F2U(A[PD(8*t + l)]);
    pbfly8<S>(v);
}

// ---------------- Kernel A: forward rfft + PHAT phase-normalize ----------------
__global__ __launch_bounds__(64) void fwd_fft_kernel(const float* __restrict__ x) {
    __shared__ float2 A[ABUF];
    int t = threadIdx.x;
    int row = blockIdx.x;
    const float2* xin = reinterpret_cast<const float2*>(x + (size_t)row * L_FFT);

    float sT, cT; sincospif((float)t * (1.0f/512.0f), &sT, &cT);  // T_t = e^{2pi i t/1024}
    float2 Tt = make_float2(cT, sT);

    ull v[8];
    #pragma unroll
    for (int l = 0; l < 8; l++) v[l] = F2U(xin[t + 64*l]);
    pbfly8<-1>(v);
    {
        float2 T2 = cmul(Tt, Tt);                  // e^{2pi i t/512}
        twiddle7(v, make_float2(T2.x, -T2.y));     // conj for forward
    }
    #pragma unroll
    for (int j = 0; j < 8; j++) A[PD(t + 64*j)] = U2F(v[j]);
    __syncthreads();

    fft_mid<-1>(A, v, t);
    __syncthreads();   // all pass-3 reads done before scatter overwrites
    // scatter Z to natural order (needed only for cross-thread mirror reads)
    int base = (t >> 3) + 8 * (t & 7);
    #pragma unroll
    for (int m = 0; m < 8; m++) A[PD(base + 64*m)] = U2F(v[m]);
    __syncthreads();

    // Unpack + normalize. Thread t outputs bins k = base + 64m; Zk comes from
    // registers (v[m]), only the mirror Zm is read from shared.
    float2* outp = g_X + (size_t)row * NBINS;
    const float2 W64t = make_float2(0.92387953251128676f, 0.38268343236508977f); // e^{i pi/8}
    float sB, cB; sincospif((float)base * (1.0f/512.0f), &sB, &cB);
    float2 Tk = make_float2(cB, sB);               // e^{2pi i base/1024}
    #pragma unroll
    for (int m = 0; m < 8; m++) {
        int k = base + 64*m;
        float2 Zk = U2F(v[m]);
        float2 Zm = A[PD((512 - k) & 511)];
        float2 Ze = make_float2(0.5f * (Zk.x + Zm.x), 0.5f * (Zk.y - Zm.y));
        float2 D  = make_float2(Zk.x - Zm.x, Zk.y + Zm.y);
        float2 Zo = make_float2(0.5f * D.y, -0.5f * D.x);
        float2 tw = make_float2(Tk.x, -Tk.y);
        float2 X  = cadd(Ze, cmul(tw, Zo));
        float inv = rsqrtf(fmaxf(X.x*X.x + X.y*X.y, 1e-30f));
        outp[k] = make_float2(X.x * inv, X.y * inv);
        Tk = cmul(Tk, W64t);
    }
    if (t == 0) {   // base == 0: bin 512 is X = Z0.x - Z0.y (real), Z0 = v[0]
        float2 Z0 = U2F(v[0]);
        float Xr = Z0.x - Z0.y;
        float inv = rsqrtf(fmaxf(Xr*Xr, 1e-30f));
        outp[512] = make_float2(Xr * inv, 0.0f);
    }
}

// ------------- Kernel B: cross-phase + OUTPUT-PRUNED 64-lag inverse real FFT -------------
__global__ __launch_bounds__(64) void xcorr_kernel(float* __restrict__ out) {
    __shared__ float2 A[ABUF];
    int t = threadIdx.x;
    int id = blockIdx.x;                 // ((b*28 + p)*250 + tt)
    int tt = id % NT;
    int pr = (id / NT) % NPAIRS;
    int b  = id / (NT * NPAIRS);

    const float2* X1 = g_X + (((size_t)(b * NCH + c_i1[pr])) * NT + tt) * NBINS;
    const float2* X2 = g_X + (((size_t)(b * NCH + c_i2[pr])) * NT + tt) * NBINS;

    float sT, cT; sincospif((float)t * (1.0f/512.0f), &sT, &cT);
    float2 Tt = make_float2(cT, sT);
    const float2 W64t = make_float2(0.92387953251128676f, 0.38268343236508977f);

    // Partner-exchange Z-build: thread t's pass-1 slots are k = t+64i.
    // It computes Z[k] for i=0..3 itself (keeps in regs v[0..3]); the mirror
    // Z[512-k] belongs to thread 64-t (regs 7-i) and goes through shared.
    ull v[8];
    float2 Tk = Tt;
    #pragma unroll
    for (int i = 0; i < 4; i++) {
        int k  = t + 64*i;          // k in [0,256)
        int km = 512 - k;
        float2 a1 = X1[k],  c1 = X2[k];
        float2 a2 = X1[km], c2 = X2[km];
        float2 Ra = make_float2(a1.x*c1.x + a1.y*c1.y, a1.y*c1.x - a1.x*c1.y);
        float2 Rb = make_float2(a2.x*c2.x + a2.y*c2.y, a2.y*c2.x - a2.x*c2.y);
        // Z[k] from (Ra, Rb) with T_k  -> own register
        float2 Ze = make_float2(0.5f*(Ra.x + Rb.x), 0.5f*(Ra.y - Rb.y));
        float2 U  = make_float2(0.5f*(Ra.x - Rb.x), 0.5f*(Ra.y + Rb.y));
        float2 Zo = cmul(Tk, U);
        v[i] = F2U(make_float2(Ze.x - Zo.y, Ze.y + Zo.x));
        if (k > 0) {
            // Z[512-k] from (Rb, Ra) with T_{512-k} = (-Tk.x, Tk.y) -> partner
            float2 Ze2 = make_float2(0.5f*(Rb.x + Ra.x), 0.5f*(Rb.y - Ra.y));
            float2 U2  = make_float2(0.5f*(Rb.x - Ra.x), 0.5f*(Rb.y + Ra.y));
            float2 Zo2 = cmul(make_float2(-Tk.x, Tk.y), U2);
            A[PD(km)] = make_float2(Ze2.x - Zo2.y, Ze2.y + Zo2.x);
        }
        Tk = cmul(Tk, W64t);
    }
    if (t == 0) {   // slot 256: Z[256] = conj(R[256])
        float2 a = X1[256], c = X2[256];
        A[PD(256)] = make_float2(a.x*c.x + a.y*c.y, -(a.y*c.x - a.x*c.y));
    }
    __syncthreads();
    #pragma unroll
    for (int i = 4; i < 8; i++) v[i] = F2U(A[PD(t + 64*i)]);

    // ---- pass 1 (full) ----
    pbfly8<1>(v);
    {
        float2 T2 = cmul(Tt, Tt);   // e^{+2pi i t/512}
        twiddle7(v, T2);
    }
    __syncthreads();   // partner loads complete before pass-1 stores overwrite
    #pragma unroll
    for (int j = 0; j < 8; j++) A[PD(t + 64*j)] = U2F(v[j]);
    __syncthreads();

    // ---- pass 2 (all butterflies, but only outputs l in {0,1,6,7} survive) ----
    {
        int n3 = t & 7;
        int b2 = 64 * (t >> 3) + n3;
        #pragma unroll
        for (int l = 0; l < 8; l++) v[l] = F2U(A[PD(b2 + 8*l)]);
        pbfly8<1>(v);
        float2 w  = c_w64[n3];            // e^{+2pi i n3/64}
        float2 w2 = cmul(w,  w);
        float2 w3 = cmul(w2, w);
        float2 w6 = cmul(w3, w3);
        float2 w7 = cmul(w6, w);
        v[1] = F2U(cmul(U2F(v[1]), w));
        v[6] = F2U(cmul(U2F(v[6]), w6));
        v[7] = F2U(cmul(U2F(v[7]), w7));
    }
    __syncthreads();   // pass-2 reads done before pruned stores overwrite
    {
        int n3 = t & 7;
        int b2 = 64 * (t >> 3) + n3;
        A[PD(b2)]      = U2F(v[0]);
        A[PD(b2 + 8)]  = U2F(v[1]);
        A[PD(b2 + 48)] = U2F(v[6]);
        A[PD(b2 + 56)] = U2F(v[7]);
    }
    __syncthreads();

    // ---- pass 3 (pruned): thread t needs only output m=0 (r<2) or m=7 (r>5) ----
    int r = t & 7;
    if (r < 2 || r > 5) {
        // contiguous: PD(8t + l) = 9t + l
        ull in[8];
        #pragma unroll
        for (int l = 0; l < 8; l++) in[l] = F2U(A[9*t + l]);

        ull z;
        if (r < 2) {
            // m = 0: plain sum
            z = padd(padd(padd(in[0], in[1]), padd(in[2], in[3])),
                     padd(padd(in[4], in[5]), padd(in[6], in[7])));
        } else {
            // m = 7 (S=+1): sum_l in[l] * w8^{-l},  w8 = e^{+2pi i/8}
            const float Cc = 0.70710678118654752440f;
            const ull CC  = F2U(make_float2( Cc,  Cc));
            const ull CCn = F2U(make_float2(-Cc, -Cc));
            ull d0 = psub(in[0], in[4]);
            ull d1 = psub(in[1], in[5]);
            ull d2 = psub(in[2], in[6]);
            ull d3 = psub(in[3], in[7]);
            ull e1 = pmulp(CC,  padd(d1, muli<-1>(d1)));  // d1 * (C - Ci)
            ull e2 = muli<-1>(d2);                        // d2 * (-i)
            ull e3 = pmulp(CCn, padd(d3, muli< 1>(d3)));  // d3 * (-C - Ci)
            z = padd(padd(d0, e1), padd(e2, e3));
        }

        // n = (t>>3) + 8*r + 64*m ; x[2n]=Re z/512, x[2n+1]=Im z/512;
        // fftshift slice: n<16 -> orow[n+16], n>=496 -> orow[n-496].
        const float sc = 1.0f / 512.0f;
        float2 zz = U2F(z);
        float2* orow = reinterpret_cast<float2*>(out + (size_t)id * NLAGS);
        int q = t >> 3;
        if (r < 2) {
            int n = q + 8*r;            // in [0,16)
            orow[n + 16] = make_float2(zz.x * sc, zz.y * sc);
        } else {
            int n = 448 + q + 8*r;      // in [496,512)
            orow[n - 496] = make_float2(zz.x * sc, zz.y * sc);
        }
    }
}

extern "C" void kernel_launch(void* const* d_in, const int* in_sizes, int n_in,
                              void* d_out, int out_size) {
    const float* x = (const float*)d_in[0];
    float* out = (float*)d_out;
    fwd_fft_kernel<<<NBATCH * NCH * NT, 64>>>(x);
    xcorr_kernel<<<NBATCH * NPAIRS * NT, 64>>>(out);
}

// round 8
// speedup vs baseline: 3.2008x; 1.0659x over previous
#include <cuda_runtime.h>
#include <cuda_bf16.h>
#include <cuda_fp16.h>

#define L_FFT   1024
#define NBINS   513
#define NBATCH  16
#define NCH     8
#define NT      250
#define NPAIRS  28
#define NLAGS   64

typedef unsigned long long ull;

// Scratch: PHASE-NORMALIZED spectra (unit magnitude) in fp16 complex. ~66 MB.
__device__ __half2 g_X[(size_t)NBATCH * NCH * NT * NBINS];

__constant__ int c_i1[NPAIRS] = {0,0,0,0,0,0,0,1,1,1,1,1,1,2,2,2,2,2,3,3,3,3,4,4,4,5,5,6};
__constant__ int c_i2[NPAIRS] = {1,2,3,4,5,6,7,2,3,4,5,6,7,3,4,5,6,7,4,5,6,7,5,6,7,6,7,7};

// Pass-2 twiddle LUT: e^{2 pi i j / 64}, j = 0..7
__constant__ float2 c_w64[8] = {
    {1.0f, 0.0f},
    {0.99518472667219689f, 0.09801714032956060f},
    {0.98078528040323045f, 0.19509032201612827f},
    {0.95694033573220887f, 0.29028467725446234f},
    {0.92387953251128676f, 0.38268343236508977f},
    {0.88192126434835503f, 0.47139673682599764f},
    {0.83146961230254524f, 0.55557023301960222f},
    {0.77301045336273696f, 0.63439328416364549f}
};

union C64u { float2 f; ull u; };
__device__ __forceinline__ ull   F2U(float2 a){ C64u c; c.f=a; return c.u; }
__device__ __forceinline__ float2 U2F(ull a){ C64u c; c.u=a; return c.f; }

// Packed f32x2 ops (sm_100+): one instruction per complex add/sub.
__device__ __forceinline__ ull padd(ull a, ull b){ ull r; asm("add.rn.f32x2 %0,%1,%2;" : "=l"(r) : "l"(a), "l"(b)); return r; }
__device__ __forceinline__ ull psub(ull a, ull b){ ull r; asm("sub.rn.f32x2 %0,%1,%2;" : "=l"(r) : "l"(a), "l"(b)); return r; }
__device__ __forceinline__ ull pmulp(ull a, ull b){ ull r; asm("mul.rn.f32x2 %0,%1,%2;" : "=l"(r) : "l"(a), "l"(b)); return r; }

__device__ __forceinline__ float2 cadd(float2 a, float2 b){ return make_float2(a.x+b.x, a.y+b.y); }
__device__ __forceinline__ float2 cmul(float2 a, float2 b){ return make_float2(a.x*b.x - a.y*b.y, a.x*b.y + a.y*b.x); }

// multiply by S*i  (S=+1: i, S=-1: -i)
template<int S>
__device__ __forceinline__ ull muli(ull a){
    float2 f = U2F(a);
    return F2U(S > 0 ? make_float2(-f.y, f.x) : make_float2(f.y, -f.x));
}

// Bank-conflict padding: one extra float2 every 8.
#define PD(i) ((i) + ((i) >> 3))
#define ABUF  576

// Natural-order radix-8 butterfly on packed complexes. S=-1 fwd, S=+1 inv.
template<int S>
__device__ __forceinline__ void pbfly8(ull v[8]) {
    const float Cc = 0.70710678118654752440f;
    const ull CC = F2U(make_float2(Cc, Cc));
    ull t0 = padd(v[0], v[4]), t4 = psub(v[0], v[4]);
    ull t1 = padd(v[1], v[5]), t5 = psub(v[1], v[5]);
    ull t2 = padd(v[2], v[6]), t6 = psub(v[2], v[6]);
    ull t3 = padd(v[3], v[7]), t7 = psub(v[3], v[7]);
    ull u5 = pmulp(CC, padd(t5, muli<S>(t5)));
    ull u6 = muli<S>(t6);
    ull u7 = pmulp(CC, psub(muli<S>(t7), t7));
    ull p0 = padd(t0, t2), q0 = psub(t0, t2);
    ull p1 = padd(t1, t3), q1 = muli<S>(psub(t1, t3));
    v[0] = padd(p0, p1); v[4] = psub(p0, p1);
    v[2] = padd(q0, q1); v[6] = psub(q0, q1);
    ull r0 = padd(t4, u6), s0 = psub(t4, u6);
    ull r1 = padd(u5, u7), s1 = muli<S>(psub(u5, u7));
    v[1] = padd(r0, r1); v[5] = psub(r0, r1);
    v[3] = padd(s0, s1); v[7] = psub(s0, s1);
}

// v[j] *= w^j, j=1..7 (shallow power tree).
__device__ __forceinline__ void twiddle7(ull v[8], float2 w){
    float2 w2 = cmul(w,  w);
    float2 w3 = cmul(w2, w);
    float2 w4 = cmul(w2, w2);
    float2 w5 = cmul(w3, w2);
    float2 w6 = cmul(w3, w3);
    float2 w7 = cmul(w4, w3);
    v[1] = F2U(cmul(U2F(v[1]), w));
    v[2] = F2U(cmul(U2F(v[2]), w2));
    v[3] = F2U(cmul(U2F(v[3]), w3));
    v[4] = F2U(cmul(U2F(v[4]), w4));
    v[5] = F2U(cmul(U2F(v[5]), w5));
    v[6] = F2U(cmul(U2F(v[6]), w6));
    v[7] = F2U(cmul(U2F(v[7]), w7));
}

// Passes 2+3 of the 512-pt register FFT (full version, used by fwd kernel).
template<int S>
__device__ __forceinline__ void fft_mid(float2* A, ull v[8], int t){
    int n3 = t & 7;
    int b2 = 64 * (t >> 3) + n3;
    #pragma unroll
    for (int l = 0; l < 8; l++) v[l] = F2U(A[PD(b2 + 8*l)]);
    pbfly8<S>(v);
    {
        float2 w = c_w64[n3];
        twiddle7(v, S > 0 ? w : make_float2(w.x, -w.y));
    }
    #pragma unroll
    for (int l = 0; l < 8; l++) A[PD(b2 + 8*l)] = U2F(v[l]);
    __syncthreads();
    #pragma unroll
    for (int l = 0; l < 8; l++) v[l] = F2U(A[PD(8*t + l)]);
    pbfly8<S>(v);
}

// ---------------- Kernel A: forward rfft + PHAT phase-normalize ----------------
__global__ __launch_bounds__(64) void fwd_fft_kernel(const float* __restrict__ x) {
    __shared__ float2 A[ABUF];
    int t = threadIdx.x;
    int row = blockIdx.x;
    const float2* xin = reinterpret_cast<const float2*>(x + (size_t)row * L_FFT);

    float sT, cT; sincospif((float)t * (1.0f/512.0f), &sT, &cT);  // T_t = e^{2pi i t/1024}
    float2 Tt = make_float2(cT, sT);

    ull v[8];
    #pragma unroll
    for (int l = 0; l < 8; l++) v[l] = F2U(xin[t + 64*l]);
    pbfly8<-1>(v);
    {
        float2 T2 = cmul(Tt, Tt);                  // e^{2pi i t/512}
        twiddle7(v, make_float2(T2.x, -T2.y));     // conj for forward
    }
    #pragma unroll
    for (int j = 0; j < 8; j++) A[PD(t + 64*j)] = U2F(v[j]);
    __syncthreads();

    fft_mid<-1>(A, v, t);
    __syncthreads();   // all pass-3 reads done before scatter overwrites
    // scatter Z to natural order (needed only for cross-thread mirror reads)
    int base = (t >> 3) + 8 * (t & 7);
    #pragma unroll
    for (int m = 0; m < 8; m++) A[PD(base + 64*m)] = U2F(v[m]);
    __syncthreads();

    // Unpack + normalize; store unit-magnitude phase as fp16 complex.
    __half2* outp = g_X + (size_t)row * NBINS;
    const float2 W64t = make_float2(0.92387953251128676f, 0.38268343236508977f); // e^{i pi/8}
    float sB, cB; sincospif((float)base * (1.0f/512.0f), &sB, &cB);
    float2 Tk = make_float2(cB, sB);               // e^{2pi i base/1024}
    #pragma unroll
    for (int m = 0; m < 8; m++) {
        int k = base + 64*m;
        float2 Zk = U2F(v[m]);
        float2 Zm = A[PD((512 - k) & 511)];
        float2 Ze = make_float2(0.5f * (Zk.x + Zm.x), 0.5f * (Zk.y - Zm.y));
        float2 D  = make_float2(Zk.x - Zm.x, Zk.y + Zm.y);
        float2 Zo = make_float2(0.5f * D.y, -0.5f * D.x);
        float2 tw = make_float2(Tk.x, -Tk.y);
        float2 X  = cadd(Ze, cmul(tw, Zo));
        float inv = rsqrtf(fmaxf(X.x*X.x + X.y*X.y, 1e-30f));
        outp[k] = __floats2half2_rn(X.x * inv, X.y * inv);
        Tk = cmul(Tk, W64t);
    }
    if (t == 0) {   // base == 0: bin 512 is X = Z0.x - Z0.y (real), Z0 = v[0]
        float2 Z0 = U2F(v[0]);
        float Xr = Z0.x - Z0.y;
        float inv = rsqrtf(fmaxf(Xr*Xr, 1e-30f));
        outp[512] = __floats2half2_rn(Xr * inv, 0.0f);
    }
}

// ------------- Kernel B: cross-phase + OUTPUT-PRUNED 64-lag inverse real FFT -------------
__global__ __launch_bounds__(64) void xcorr_kernel(float* __restrict__ out) {
    __shared__ float2 A[ABUF];
    int t = threadIdx.x;
    int id = blockIdx.x;                 // ((b*28 + p)*250 + tt)
    int tt = id % NT;
    int pr = (id / NT) % NPAIRS;
    int b  = id / (NT * NPAIRS);

    const __half2* X1 = g_X + (((size_t)(b * NCH + c_i1[pr])) * NT + tt) * NBINS;
    const __half2* X2 = g_X + (((size_t)(b * NCH + c_i2[pr])) * NT + tt) * NBINS;

    float sT, cT; sincospif((float)t * (1.0f/512.0f), &sT, &cT);
    float2 Tt = make_float2(cT, sT);
    const float2 W64t = make_float2(0.92387953251128676f, 0.38268343236508977f);

    // Partner-exchange Z-build: thread t's pass-1 slots are k = t+64i.
    // It computes Z[k] for i=0..3 itself (keeps in regs v[0..3]); the mirror
    // Z[512-k] belongs to thread 64-t (regs 7-i) and goes through shared.
    ull v[8];
    float2 Tk = Tt;
    #pragma unroll
    for (int i = 0; i < 4; i++) {
        int k  = t + 64*i;          // k in [0,256)
        int km = 512 - k;
        float2 a1 = __half22float2(X1[k]);
        float2 c1 = __half22float2(X2[k]);
        float2 a2 = __half22float2(X1[km]);
        float2 c2 = __half22float2(X2[km]);
        float2 Ra = make_float2(a1.x*c1.x + a1.y*c1.y, a1.y*c1.x - a1.x*c1.y);
        float2 Rb = make_float2(a2.x*c2.x + a2.y*c2.y, a2.y*c2.x - a2.x*c2.y);
        // Z[k] from (Ra, Rb) with T_k  -> own register
        float2 Ze = make_float2(0.5f*(Ra.x + Rb.x), 0.5f*(Ra.y - Rb.y));
        float2 U  = make_float2(0.5f*(Ra.x - Rb.x), 0.5f*(Ra.y + Rb.y));
        float2 Zo = cmul(Tk, U);
        v[i] = F2U(make_float2(Ze.x - Zo.y, Ze.y + Zo.x));
        if (k > 0) {
            // Z[512-k] from (Rb, Ra) with T_{512-k} = (-Tk.x, Tk.y) -> partner
            float2 Ze2 = make_float2(0.5f*(Rb.x + Ra.x), 0.5f*(Rb.y - Ra.y));
            float2 U2  = make_float2(0.5f*(Rb.x - Ra.x), 0.5f*(Rb.y + Ra.y));
            float2 Zo2 = cmul(make_float2(-Tk.x, Tk.y), U2);
            A[PD(km)] = make_float2(Ze2.x - Zo2.y, Ze2.y + Zo2.x);
        }
        Tk = cmul(Tk, W64t);
    }
    if (t == 0) {   // slot 256: Z[256] = conj(R[256])
        float2 a = __half22float2(X1[256]);
        float2 c = __half22float2(X2[256]);
        A[PD(256)] = make_float2(a.x*c.x + a.y*c.y, -(a.y*c.x - a.x*c.y));
    }
    __syncthreads();
    #pragma unroll
    for (int i = 4; i < 8; i++) v[i] = F2U(A[PD(t + 64*i)]);

    // ---- pass 1 (full) ----
    pbfly8<1>(v);
    {
        float2 T2 = cmul(Tt, Tt);   // e^{+2pi i t/512}
        twiddle7(v, T2);
    }
    __syncthreads();   // partner loads complete before pass-1 stores overwrite
    #pragma unroll
    for (int j = 0; j < 8; j++) A[PD(t + 64*j)] = U2F(v[j]);
    __syncthreads();

    // ---- pass 2 (all butterflies, but only outputs l in {0,1,6,7} survive) ----
    {
        int n3 = t & 7;
        int b2 = 64 * (t >> 3) + n3;
        #pragma unroll
        for (int l = 0; l < 8; l++) v[l] = F2U(A[PD(b2 + 8*l)]);
        pbfly8<1>(v);
        float2 w  = c_w64[n3];            // e^{+2pi i n3/64}
        float2 w2 = cmul(w,  w);
        float2 w3 = cmul(w2, w);
        float2 w6 = cmul(w3, w3);
        float2 w7 = cmul(w6, w);
        v[1] = F2U(cmul(U2F(v[1]), w));
        v[6] = F2U(cmul(U2F(v[6]), w6));
        v[7] = F2U(cmul(U2F(v[7]), w7));
    }
    __syncthreads();   // pass-2 reads done before pruned stores overwrite
    {
        int n3 = t & 7;
        int b2 = 64 * (t >> 3) + n3;
        A[PD(b2)]      = U2F(v[0]);
        A[PD(b2 + 8)]  = U2F(v[1]);
        A[PD(b2 + 48)] = U2F(v[6]);
        A[PD(b2 + 56)] = U2F(v[7]);
    }
    __syncthreads();

    // ---- pass 3 (pruned): thread t needs only output m=0 (r<2) or m=7 (r>5) ----
    int r = t & 7;
    if (r < 2 || r > 5) {
        // contiguous: PD(8t + l) = 9t + l
        ull in[8];
        #pragma unroll
        for (int l = 0; l < 8; l++) in[l] = F2U(A[9*t + l]);

        ull z;
        if (r < 2) {
            // m = 0: plain sum
            z = padd(padd(padd(in[0], in[1]), padd(in[2], in[3])),
                     padd(padd(in[4], in[5]), padd(in[6], in[7])));
        } else {
            // m = 7 (S=+1): sum_l in[l] * w8^{-l},  w8 = e^{+2pi i/8}
            const float Cc = 0.70710678118654752440f;
            const ull CC  = F2U(make_float2( Cc,  Cc));
            const ull CCn = F2U(make_float2(-Cc, -Cc));
            ull d0 = psub(in[0], in[4]);
            ull d1 = psub(in[1], in[5]);
            ull d2 = psub(in[2], in[6]);
            ull d3 = psub(in[3], in[7]);
            ull e1 = pmulp(CC,  padd(d1, muli<-1>(d1)));  // d1 * (C - Ci)
            ull e2 = muli<-1>(d2);                        // d2 * (-i)
            ull e3 = pmulp(CCn, padd(d3, muli< 1>(d3)));  // d3 * (-C - Ci)
            z = padd(padd(d0, e1), padd(e2, e3));
        }

        // n = (t>>3) + 8*r + 64*m ; x[2n]=Re z/512, x[2n+1]=Im z/512;
        // fftshift slice: n<16 -> orow[n+16], n>=496 -> orow[n-496].
        const float sc = 1.0f / 512.0f;
        float2 zz = U2F(z);
        float2* orow = reinterpret_cast<float2*>(out + (size_t)id * NLAGS);
        int q = t >> 3;
        if (r < 2) {
            int n = q + 8*r;            // in [0,16)
            orow[n + 16] = make_float2(zz.x * sc, zz.y * sc);
        } else {
            int n = 448 + q + 8*r;      // in [496,512)
            orow[n - 496] = make_float2(zz.x * sc, zz.y * sc);
        }
    }
}

extern "C" void kernel_launch(void* const* d_in, const int* in_sizes, int n_in,
                              void* d_out, int out_size) {
    const float* x = (const float*)d_in[0];
    float* out = (float*)d_out;
    fwd_fft_kernel<<<NBATCH * NCH * NT, 64>>>(x);
    xcorr_kernel<<<NBATCH * NPAIRS * NT, 64>>>(out);
}